// round 8
// baseline (speedup 1.0000x reference)
#include <cuda_runtime.h>

#define DIM    768
#define NEXP   8
#define PARTS  8                      // threads cooperating per token
#define TOKS   2                      // tokens per thread (regs ~90 -> 2x occupancy)
#define JITER  (DIM / (PARTS * 4))    // float4 steps per part = 24
#define TPB    128

// Packed fp32x2 math (Blackwell): one instruction, two fp32 FMAs.
__device__ __forceinline__ unsigned long long ffma2(unsigned long long a,
                                                    unsigned long long b,
                                                    unsigned long long c) {
    unsigned long long d;
    asm("fma.rn.f32x2 %0, %1, %2, %3;" : "=l"(d) : "l"(a), "l"(b), "l"(c));
    return d;
}
__device__ __forceinline__ unsigned long long fadd2(unsigned long long a,
                                                    unsigned long long b) {
    unsigned long long d;
    asm("add.rn.f32x2 %0, %1, %2;" : "=l"(d) : "l"(a), "l"(b));
    return d;
}

__global__ __launch_bounds__(TPB)
void Router_54932631716286_kernel(const float* __restrict__ x,
                                  const float* __restrict__ W,
                                  const float* __restrict__ b,
                                  float* __restrict__ out,
                                  int n_tokens)
{
    // W: 8 x 768 fp32 = 24 KB staged in smem. Within a warp all 4 token-groups
    // are at the same i, so one LDS.128 = 8 distinct 16B x 4-way broadcast
    // = 128B unique -> full-crossbar, conflict-free.
    __shared__ float4 sW4[NEXP * DIM / 4];
    __shared__ float  sb[NEXP];

    const float4* W4 = reinterpret_cast<const float4*>(W);
    for (int i = threadIdx.x; i < NEXP * DIM / 4; i += TPB) sW4[i] = W4[i];
    if (threadIdx.x < NEXP) sb[threadIdx.x] = b[threadIdx.x];
    __syncthreads();

    int gtid  = blockIdx.x * TPB + threadIdx.x;
    int group = gtid >> 3;            // 8 consecutive lanes share a 2-token group
    int part  = gtid & 7;
    int t0    = group * TOKS;

    if (t0 >= n_tokens) return;       // group-aligned warp exit

    int tr1 = (t0 + 1 < n_tokens) ? t0 + 1 : t0;   // ragged-tail clamp

    const ulonglong2* xr0 = reinterpret_cast<const ulonglong2*>(x + (size_t)t0  * DIM);
    const ulonglong2* xr1 = reinterpret_cast<const ulonglong2*>(x + (size_t)tr1 * DIM);
    const ulonglong2* wp  = reinterpret_cast<const ulonglong2*>(sW4);

    unsigned long long acc[NEXP][TOKS];
#pragma unroll
    for (int e = 0; e < NEXP; e++)
#pragma unroll
        for (int t = 0; t < TOKS; t++) acc[e][t] = 0ull;

    // Software prefetch: issue next iteration's 2 LDG.128 before this
    // iteration's FMA chain so loads stay ahead of consumption.
    int i = part;
    ulonglong2 nx0 = xr0[i];
    ulonglong2 nx1 = xr1[i];
#pragma unroll
    for (int j = 0; j < JITER; j++) {
        ulonglong2 x0 = nx0;
        ulonglong2 x1 = nx1;
        if (j + 1 < JITER) {
            nx0 = xr0[i + PARTS];
            nx1 = xr1[i + PARTS];
        }
#pragma unroll
        for (int e = 0; e < NEXP; e++) {
            ulonglong2 wv = wp[e * (DIM / 4) + i];
            acc[e][0] = ffma2(x0.x, wv.x, ffma2(x0.y, wv.y, acc[e][0]));
            acc[e][1] = ffma2(x1.x, wv.x, ffma2(x1.y, wv.y, acc[e][1]));
        }
        i += PARTS;
    }

    // Reduce the 8 part-partials (consecutive lanes) via butterfly shuffles.
#pragma unroll
    for (int e = 0; e < NEXP; e++) {
#pragma unroll
        for (int t = 0; t < TOKS; t++) {
            unsigned long long v = acc[e][t];
            v = fadd2(v, __shfl_xor_sync(0xffffffffu, v, 1));
            v = fadd2(v, __shfl_xor_sync(0xffffffffu, v, 2));
            v = fadd2(v, __shfl_xor_sync(0xffffffffu, v, 4));
            acc[e][t] = v;
        }
    }

    if (part != 0) return;

    // Epilogue: one lane per group -> softmax + top-2 for its 2 tokens.
    float4 gv, iv;
    float* gvf = reinterpret_cast<float*>(&gv);
    float* ivf = reinterpret_cast<float*>(&iv);

#pragma unroll
    for (int t = 0; t < TOKS; t++) {
        float logits[NEXP];
        float m = -1e30f;
#pragma unroll
        for (int e = 0; e < NEXP; e++) {
            float lo = __uint_as_float((unsigned)(acc[e][t] & 0xffffffffull));
            float hi = __uint_as_float((unsigned)(acc[e][t] >> 32));
            logits[e] = lo + hi + sb[e];
            m = fmaxf(m, logits[e]);
        }
        float g[NEXP], s = 0.f;
#pragma unroll
        for (int e = 0; e < NEXP; e++) { g[e] = __expf(logits[e] - m); s += g[e]; }
        float inv = 1.0f / s;
#pragma unroll
        for (int e = 0; e < NEXP; e++) g[e] *= inv;

        // Top-2, strict '>' keeps lowest index on ties (matches jax.lax.top_k).
        int i1 = 0; float g1 = g[0];
#pragma unroll
        for (int e = 1; e < NEXP; e++) if (g[e] > g1) { g1 = g[e]; i1 = e; }
        int i2 = -1; float g2 = -1e30f;
#pragma unroll
        for (int e = 0; e < NEXP; e++) if (e != i1 && g[e] > g2) { g2 = g[e]; i2 = e; }

        gvf[2 * t + 0] = g1;
        gvf[2 * t + 1] = g2;
        ivf[2 * t + 0] = (float)i1;
        ivf[2 * t + 1] = (float)i2;
    }

    // Output: [0,2N) top-2 gates, [2N,4N) indices as fp32 (exact integers).
    // t0 is even -> out + t0*2 is 16B aligned -> single float4 per stream.
    float* og = out + (size_t)t0 * 2;
    float* oi = out + (size_t)2 * n_tokens + (size_t)t0 * 2;
    if (t0 + TOKS <= n_tokens) {
        *reinterpret_cast<float4*>(og) = gv;
        *reinterpret_cast<float4*>(oi) = iv;
    } else {
        og[0] = gvf[0]; og[1] = gvf[1];
        oi[0] = ivf[0]; oi[1] = ivf[1];
    }
}

extern "C" void kernel_launch(void* const* d_in, const int* in_sizes, int n_in,
                              void* d_out, int out_size) {
    const float* x = (const float*)d_in[0];
    const float* W = (const float*)d_in[1];
    const float* b = (const float*)d_in[2];
    float* out = (float*)d_out;

    int n_tokens = in_sizes[0] / DIM;                  // 128*197 = 25216
    int groups   = (n_tokens + TOKS - 1) / TOKS;       // 12608
    int threads  = groups * PARTS;                     // 100864
    int blocks   = (threads + TPB - 1) / TPB;          // 788

    Router_54932631716286_kernel<<<blocks, TPB>>>(x, W, b, out, n_tokens);
}